// round 7
// baseline (speedup 1.0000x reference)
#include <cuda_runtime.h>
#include <cuda_bf16.h>
#include <cstdint>

#define BB 64
#define SS 512
#define HH 768
#define LL 9

__device__ float g_feats[(size_t)BB * SS * LL];
__device__ float g_part[BB];
__device__ int   g_cnt;

__device__ __forceinline__ float ex2f_(float x) {
    float y; asm("ex2.approx.ftz.f32 %0, %1;" : "=f"(y) : "f"(x)); return y;
}
__device__ __forceinline__ float lg2f_(float x) {
    float y; asm("lg2.approx.f32 %0, %1;" : "=f"(y) : "f"(x)); return y;
}

// ---------------------------------------------------------------------------
// Kernel 1: feats[m][l] = hidden[m][:] . W[l][:] + b[l]   (M=32768,K=768,N=9)
// Warp-split-K, 4 rows/warp (lanes 0-15 rows r0,r1; 16-31 rows r2,r3); lane
// sl owns K float4 slice {sl+16u}. DEPTH-3 h prefetch: 6 float4 in flight per
// lane so the ~600-cycle DRAM latency is covered by ~2 full u-rounds of FMA
// work across the resident warps. Full 12x unroll -> immediate offsets.
// LDG.128 = 4 lines/instr; W float4 LDS feeds 8 FFMA. 64-reg cap -> 4
// blocks/SM, 32 warps, grid 512 = one wave, 2 quads/warp, zero tail.
// ---------------------------------------------------------------------------
__global__ __launch_bounds__(256, 4)
void gemm_kernel(const float* __restrict__ hidden,
                 const float* __restrict__ W,
                 const float* __restrict__ bias,
                 float* __restrict__ feats) {
    __shared__ float4 ws4[LL * 192];       // 27648 B
    const int tid = threadIdx.x;
    const unsigned FULL = 0xffffffffu;

    if (blockIdx.x == 0 && tid == 0) g_cnt = 0;   // reset crf's arrival counter

    for (int i = tid; i < LL * 192; i += 256)
        ws4[i] = reinterpret_cast<const float4*>(W)[i];
    __syncthreads();

    const int gw   = blockIdx.x * 8 + (tid >> 5);   // 0..4095
    const int lane = tid & 31;
    const int half = lane >> 4;                      // row pair within quad
    const int sl   = lane & 15;                      // k-slice

#pragma unroll 1
    for (int quad = gw; quad < 8192; quad += 4096) {
        const int rowA = quad * 4 + half * 2;
        const int rowB = rowA + 1;
        const float4* hpA = reinterpret_cast<const float4*>(hidden + (size_t)rowA * HH);
        const float4* hpB = reinterpret_cast<const float4*>(hidden + (size_t)rowB * HH);

        float accA[LL], accB[LL];
#pragma unroll
        for (int l = 0; l < LL; l++) { accA[l] = 0.f; accB[l] = 0.f; }

        // depth-3 prefetch pipeline
        float4 p0a = hpA[sl],          p0b = hpB[sl];
        float4 p1a = hpA[sl + 16],     p1b = hpB[sl + 16];
        float4 p2a = hpA[sl + 32],     p2b = hpB[sl + 32];

#pragma unroll
        for (int u = 0; u < 12; ++u) {
            float4 ha = p0a, hb = p0b;
            p0a = p1a; p0b = p1b;
            p1a = p2a; p1b = p2b;
            if (u < 9) {
                p2a = hpA[sl + 16 * (u + 3)];
                p2b = hpB[sl + 16 * (u + 3)];
            }
            const float4* wrow = ws4 + sl + 16 * u;
#pragma unroll
            for (int l = 0; l < LL; ++l) {
                float4 w = wrow[l * 192];
                accA[l] = fmaf(ha.x, w.x, fmaf(ha.y, w.y,
                          fmaf(ha.z, w.z, fmaf(ha.w, w.w, accA[l]))));
                accB[l] = fmaf(hb.x, w.x, fmaf(hb.y, w.y,
                          fmaf(hb.z, w.z, fmaf(hb.w, w.w, accB[l]))));
            }
        }

        // reduce the 16-lane K-split (halves independent; xor<=8 stays inside)
#pragma unroll
        for (int l = 0; l < LL; ++l) {
            accA[l] += __shfl_xor_sync(FULL, accA[l], 8);
            accB[l] += __shfl_xor_sync(FULL, accB[l], 8);
            accA[l] += __shfl_xor_sync(FULL, accA[l], 4);
            accB[l] += __shfl_xor_sync(FULL, accB[l], 4);
            accA[l] += __shfl_xor_sync(FULL, accA[l], 2);
            accB[l] += __shfl_xor_sync(FULL, accB[l], 2);
            accA[l] += __shfl_xor_sync(FULL, accA[l], 1);
            accB[l] += __shfl_xor_sync(FULL, accB[l], 1);
        }
        if (sl == 0) {
            float* oA = feats + (size_t)rowA * LL;
            float* oB = feats + (size_t)rowB * LL;
#pragma unroll
            for (int l = 0; l < LL; ++l) {
                float b = __ldg(&bias[l]);
                oA[l] = accA[l] + b;
                oB[l] = accB[l] + b;
            }
        }
    }
}

// ---------------------------------------------------------------------------
// Kernel 2: one block (256 thr, 8 warps) per batch.
// Blocked parallel CRF scan (9x9 linear-domain transfer-matrix products per
// warp, exact power-of-2 rescale, warp 0 chains alpha through 8 matrices).
// The LAST block to finish (atomic counter) also reduces the 64 partials in
// fixed index order and writes the scalar mean -> no separate finalize kernel.
// ---------------------------------------------------------------------------
__global__ __launch_bounds__(256, 1)
void crf_kernel(const float* __restrict__ feats,
                const float* __restrict__ start_tr,
                const float* __restrict__ end_tr,
                const float* __restrict__ trans,
                const int* __restrict__ labels,
                const unsigned char* __restrict__ mask8,
                float* __restrict__ partials,
                float* __restrict__ out) {
    __shared__ float sm_ef[SS * LL];       // 18432 B: exp(feats)
    __shared__ float sm_M[8][81];
    __shared__ float sm_C[8];
    __shared__ float sm_red[8];
    __shared__ float sm_score;
    __shared__ int   sm_len;

    const int b = blockIdx.x;
    const int tid = threadIdx.x;
    const int wid = tid >> 5;
    const int lane = tid & 31;
    const unsigned FULL = 0xffffffffu;
    const float LOG2E = 1.4426950408889634f;
    const float LN2   = 0.6931471805599453f;

    // ---- sequence length (mask monotone: mask[t] = t < len) ----
    const unsigned char* mrow = mask8 + (size_t)b * SS;
    int cnt = 0;
    for (int t = tid; t < SS; t += 256) cnt += (int)mrow[t];
    cnt = __reduce_add_sync(FULL, cnt);
    if (lane == 0) sm_red[wid] = (float)cnt;
    __syncthreads();
    if (tid == 0) {
        int l = 0;
        for (int w = 0; w < 8; w++) l += (int)sm_red[w];
        sm_len = l;
    }
    __syncthreads();
    int len = sm_len;
    if (len < SS / 2) {   // fallback: mask stored as int32 (lens >= 256 if u8)
        const int* mi = reinterpret_cast<const int*>(mask8) + (size_t)b * SS;
        cnt = 0;
        for (int t = tid; t < SS; t += 256) cnt += (mi[t] != 0);
        cnt = __reduce_add_sync(FULL, cnt);
        if (lane == 0) sm_red[wid] = (float)cnt;
        __syncthreads();
        if (tid == 0) {
            int l = 0;
            for (int w = 0; w < 8; w++) l += (int)sm_red[w];
            sm_len = l;
        }
        __syncthreads();
        len = sm_len;
    }
    __syncthreads();

    // ---- ef table: sm_ef[t*9+j] = exp(feats[b][t][j]) (vectorized) ----
    const float* frow = feats + (size_t)b * SS * LL;
    for (int i = tid; i < (SS * LL) / 4; i += 256) {
        float4 v = reinterpret_cast<const float4*>(frow)[i];
        float4 e;
        e.x = ex2f_(v.x * LOG2E); e.y = ex2f_(v.y * LOG2E);
        e.z = ex2f_(v.z * LOG2E); e.w = ex2f_(v.w * LOG2E);
        reinterpret_cast<float4*>(sm_ef)[i] = e;
    }

    // ---- gold path score (block-parallel over t) ----
    const int* lab = labels + (size_t)b * SS;
    float sc = 0.f;
    for (int t = tid; t < SS; t += 256) {
        int lt = lab[t];
        if (t == 0) {
            sc += __ldg(&start_tr[lt]) + frow[lt];
        } else if (t < len) {
            sc += __ldg(&trans[lab[t - 1] * LL + lt]) + frow[t * LL + lt];
        }
        if (t == len - 1) sc += __ldg(&end_tr[lt]);
    }
#pragma unroll
    for (int o = 16; o > 0; o >>= 1) sc += __shfl_xor_sync(FULL, sc, o);
    if (lane == 0) sm_red[wid] = sc;
    __syncthreads();
    if (tid == 0) {
        float s = 0.f;
        for (int w = 0; w < 8; w++) s += sm_red[w];
        sm_score = s;
    }

    // ---- per-warp segment matrix product ----
    const int a = (lane < 27) ? (lane / 3) : 8;   // owned row
    const int g = lane % 3;                       // owned col-triple
    float Ec[LL][3];                              // E[i][3g+k]
#pragma unroll
    for (int i = 0; i < LL; i++)
#pragma unroll
        for (int k = 0; k < 3; k++)
            Ec[i][k] = __expf(__ldg(&trans[i * LL + 3 * g + k]));

    float Mr[3];
#pragma unroll
    for (int k = 0; k < 3; k++) Mr[k] = (3 * g + k == a) ? 1.f : 0.f;
    float Cw = 0.f;

    __syncthreads();  // sm_ef ready

    const int t0 = max(1, wid * 64);
    const int t1 = min(len, (wid + 1) * 64);
    for (int t = t0; t < t1; ++t) {
        float ef0 = sm_ef[t * LL + 3 * g + 0];
        float ef1 = sm_ef[t * LL + 3 * g + 1];
        float ef2 = sm_ef[t * LL + 3 * g + 2];

        float m[LL];
#pragma unroll
        for (int i = 0; i < LL; i++)
            m[i] = __shfl_sync(FULL, Mr[i % 3], a * 3 + i / 3);

        float o0a = m[0] * Ec[0][0], o0b = m[1] * Ec[1][0];
        float o1a = m[0] * Ec[0][1], o1b = m[1] * Ec[1][1];
        float o2a = m[0] * Ec[0][2], o2b = m[1] * Ec[1][2];
#pragma unroll
        for (int i = 2; i < LL; i += 2) {
            o0a = fmaf(m[i], Ec[i][0], o0a);
            o1a = fmaf(m[i], Ec[i][1], o1a);
            o2a = fmaf(m[i], Ec[i][2], o2a);
            if (i + 1 < LL) {
                o0b = fmaf(m[i + 1], Ec[i + 1][0], o0b);
                o1b = fmaf(m[i + 1], Ec[i + 1][1], o1b);
                o2b = fmaf(m[i + 1], Ec[i + 1][2], o2b);
            }
        }
        Mr[0] = (o0a + o0b) * ef0;
        Mr[1] = (o1a + o1b) * ef1;
        Mr[2] = (o2a + o2b) * ef2;

        if ((t & 7) == 7) {
            float u = __shfl_sync(FULL, Mr[0], 0);
            int e = (__float_as_int(u) >> 23) & 255;
            float scale = __int_as_float((254 - e) << 23);  // 2^(127-e)
            Mr[0] *= scale; Mr[1] *= scale; Mr[2] *= scale;
            Cw += (float)(e - 127);
        }
    }
    if (lane < 27) {
#pragma unroll
        for (int k = 0; k < 3; k++) sm_M[wid][a * LL + 3 * g + k] = Mr[k];
    }
    if (lane == 0) sm_C[wid] = Cw;
    __syncthreads();

    // ---- warp 0: chain alpha through the 8 segment matrices, then the last
    // block to arrive reduces all 64 partials (fixed order -> deterministic).
    if (wid == 0) {
        float al = (lane < LL) ? sm_ef[lane] * __expf(__ldg(&start_tr[lane])) : 0.f;
        float C = 0.f;
#pragma unroll 1
        for (int s = 0; s < 8; ++s) {
            float m[LL];
#pragma unroll
            for (int i = 0; i < LL; i++) m[i] = __shfl_sync(FULL, al, i);
            const int jj = (lane < LL) ? lane : 0;
            float sum = 0.f;
#pragma unroll
            for (int i = 0; i < LL; i++)
                sum = fmaf(m[i], sm_M[s][i * LL + jj], sum);
            al = (lane < LL) ? sum : 0.f;
            C += sm_C[s];
            float u = __shfl_sync(FULL, al, 0);
            int e = (__float_as_int(u) >> 23) & 255;
            float scale = __int_as_float((254 - e) << 23);
            al *= scale;
            C += (float)(e - 127);
        }
        float ev = (lane < LL) ? al * __expf(__ldg(&end_tr[lane])) : 0.f;
#pragma unroll
        for (int o = 16; o > 0; o >>= 1) ev += __shfl_xor_sync(FULL, ev, o);
        float logden = LN2 * (C + lg2f_(ev));

        int old = 0;
        if (lane == 0) {
            partials[b] = logden - sm_score;
            __threadfence();
            old = atomicAdd(&g_cnt, 1);
        }
        old = __shfl_sync(FULL, old, 0);
        if (old == BB - 1) {
            // last block: reduce the 64 partials (L2 reads, fixed order)
            float v = __ldcg(&partials[lane]) + __ldcg(&partials[lane + 32]);
#pragma unroll
            for (int o = 16; o > 0; o >>= 1) v += __shfl_xor_sync(FULL, v, o);
            if (lane == 0) out[0] = v * (1.0f / BB);
        }
    }
}

// ---------------------------------------------------------------------------
extern "C" void kernel_launch(void* const* d_in, const int* in_sizes, int n_in,
                              void* d_out, int out_size) {
    const float* hidden  = (const float*)d_in[0];
    const float* W       = (const float*)d_in[1];
    const float* bias    = (const float*)d_in[2];
    const float* start_t = (const float*)d_in[3];
    const float* end_t   = (const float*)d_in[4];
    const float* trans   = (const float*)d_in[5];
    const int*   labels  = (const int*)d_in[6];
    const unsigned char* mask = (const unsigned char*)d_in[7];
    float* out = (float*)d_out;

    float* feats = nullptr;
    float* part  = nullptr;
    cudaGetSymbolAddress((void**)&feats, g_feats);
    cudaGetSymbolAddress((void**)&part,  g_part);

    gemm_kernel<<<512, 256>>>(hidden, W, bias, feats);
    crf_kernel<<<BB, 256>>>(feats, start_t, end_t, trans, labels, mask, part, out);
}